// round 3
// baseline (speedup 1.0000x reference)
#include <cuda_runtime.h>
#include <math.h>

// Problem constants (fixed shapes)
#define Nn   100000
#define Ecnt 1600000
#define ET   (Ecnt + Nn)      // 1,700,000
#define NB   98               // ceil(Nn/1024)

// ---------------- scratch (device globals) ----------------
__device__ float4 g_xp[Nn * 32];      // xp [N,128] conv1 / xp2 [N,64] conv2
__device__ float4 g_h[Nn * 64];       // h = relu(concat) [N,256]
__device__ float  g_asrc[Nn * 4];
__device__ float  g_adst[Nn * 4];
__device__ int    g_deg[Nn];
__device__ int    g_cursor[Nn];
__device__ int    g_rowstart[Nn + 1];
__device__ int    g_csr[ET];
__device__ int    g_bsum[128];
__device__ int    g_boff[128];

// ---------------- packed fp32 helpers ----------------
#define FMA2(d, a, b, c) \
    asm("fma.rn.f32x2 %0, %1, %2, %3;" : "=l"(d) : "l"(a), "l"(b), "l"(c))
#define PACK2(d, v) \
    asm("mov.b64 %0, {%1, %1};" : "=l"(d) : "f"(v))

// ---------------- CSR build ----------------
__global__ void k_zero_counts() {
    int i = blockIdx.x * blockDim.x + threadIdx.x;
    if (i < Nn) { g_deg[i] = 0; g_cursor[i] = 0; }
}

__global__ void k_degree(const int* __restrict__ ei) {
    int e = blockIdx.x * blockDim.x + threadIdx.x;
    if (e >= ET) return;
    int d = (e < Ecnt) ? ei[Ecnt + e] : (e - Ecnt);
    atomicAdd(&g_deg[d], 1);
}

__global__ void k_blockscan() {
    __shared__ int sh[1024];
    int b = blockIdx.x, t = threadIdx.x;
    int i = b * 1024 + t;
    int v = (i < Nn) ? g_deg[i] : 0;
    sh[t] = v;
    __syncthreads();
    for (int off = 1; off < 1024; off <<= 1) {
        int tv = (t >= off) ? sh[t - off] : 0;
        __syncthreads();
        sh[t] += tv;
        __syncthreads();
    }
    if (i < Nn) g_rowstart[i] = sh[t] - v;
    if (t == 1023) g_bsum[b] = sh[1023];
}

__global__ void k_scansums() {
    __shared__ int sh[128];
    int t = threadIdx.x;
    int v = (t < NB) ? g_bsum[t] : 0;
    sh[t] = v;
    __syncthreads();
    for (int off = 1; off < 128; off <<= 1) {
        int tv = (t >= off) ? sh[t - off] : 0;
        __syncthreads();
        sh[t] += tv;
        __syncthreads();
    }
    g_boff[t] = sh[t] - v;
    if (t == 127) g_rowstart[Nn] = sh[127];
}

__global__ void k_addoff() {
    int b = blockIdx.x, t = threadIdx.x;
    int i = b * 1024 + t;
    if (i < Nn) g_rowstart[i] += g_boff[b];
}

__global__ void k_fill(const int* __restrict__ ei) {
    int e = blockIdx.x * blockDim.x + threadIdx.x;
    if (e >= ET) return;
    int s, d;
    if (e < Ecnt) { s = ei[e]; d = ei[Ecnt + e]; }
    else          { s = d = e - Ecnt; }
    int pos = atomicAdd(&g_cursor[d], 1);
    g_csr[g_rowstart[d] + pos] = s;
}

// ---------------- GEMM: XP = X @ W, fused attention-dot epilogue ----------------
// 256 threads. 8 output cols per thread (4 f32x2 col-pairs). W K-major in smem:
// each thread's 8 cols load as 2x lds.128 = 4 natural u64 pairs -> zero packing
// on W; only the x broadcast needs a mov.b64 {f,f} (1 pack per 4 FFMA2).
// Epilogue: lanes sharing a row (CG of them) shfl-reduce att dots -> g_asrc/g_adst.
template <int K, int NCOL, int RPT, int HEADS_T, bool IN_H>
__global__ void k_gemm(const float* __restrict__ Xext, const float* __restrict__ W,
                       const float* __restrict__ att_src, const float* __restrict__ att_dst,
                       int ntiles) {
    constexpr int CG = NCOL / 8;      // threads covering one row
    constexpr int RG = 256 / CG;      // row groups
    constexpr int ROWS = RG * RPT;    // rows per tile (32)
    constexpr int LPH = CG / HEADS_T; // lanes per head
    extern __shared__ float sm[];
    float* Ws = sm;                   // [K][NCOL]
    float* Xs = sm + K * NCOL;        // [ROWS][K]
    const float* X = IN_H ? (const float*)g_h : Xext;
    float* XP = (float*)g_xp;

    int t = threadIdx.x;
    for (int i = t; i < K * NCOL / 4; i += 256)
        ((float4*)Ws)[i] = ((const float4*)W)[i];

    int cg = t % CG;
    int rg = t / CG;

    float asv[8], adv[8];
#pragma unroll
    for (int i = 0; i < 8; i++) { asv[i] = att_src[cg * 8 + i]; adv[i] = att_dst[cg * 8 + i]; }

    for (int tile = blockIdx.x; tile < ntiles; tile += gridDim.x) {
        __syncthreads();
        const float4* Xg = (const float4*)(X + (size_t)tile * ROWS * K);
        for (int i = t; i < ROWS * K / 4; i += 256)
            ((float4*)Xs)[i] = Xg[i];
        __syncthreads();

        unsigned long long acc[RPT][4];
#pragma unroll
        for (int j = 0; j < RPT; j++)
#pragma unroll
            for (int c = 0; c < 4; c++) acc[j][c] = 0ULL;

#pragma unroll 2
        for (int k4 = 0; k4 < K / 4; k4++) {
            float xa[RPT][4];
#pragma unroll
            for (int j = 0; j < RPT; j++) {
                float4 xv = *(const float4*)&Xs[(rg * RPT + j) * K + k4 * 4];
                xa[j][0] = xv.x; xa[j][1] = xv.y; xa[j][2] = xv.z; xa[j][3] = xv.w;
            }
#pragma unroll
            for (int kk = 0; kk < 4; kk++) {
                const ulonglong2* wp = (const ulonglong2*)&Ws[(k4 * 4 + kk) * NCOL + cg * 8];
                ulonglong2 w0 = wp[0];
                ulonglong2 w1 = wp[1];
#pragma unroll
                for (int j = 0; j < RPT; j++) {
                    unsigned long long xq;
                    PACK2(xq, xa[j][kk]);
                    FMA2(acc[j][0], w0.x, xq, acc[j][0]);
                    FMA2(acc[j][1], w0.y, xq, acc[j][1]);
                    FMA2(acc[j][2], w1.x, xq, acc[j][2]);
                    FMA2(acc[j][3], w1.y, xq, acc[j][3]);
                }
            }
        }

#pragma unroll
        for (int j = 0; j < RPT; j++) {
            int row = tile * ROWS + rg * RPT + j;
            const float* fa = (const float*)acc[j];   // 8 cols: cg*8 .. cg*8+7
            float4* Og = (float4*)(XP + (size_t)row * NCOL + cg * 8);
            Og[0] = make_float4(fa[0], fa[1], fa[2], fa[3]);
            Og[1] = make_float4(fa[4], fa[5], fa[6], fa[7]);
            // fused attention dots
            float s = 0.f, dd = 0.f;
#pragma unroll
            for (int i = 0; i < 8; i++) { s = fmaf(fa[i], asv[i], s); dd = fmaf(fa[i], adv[i], dd); }
#pragma unroll
            for (int off = LPH / 2; off; off >>= 1) {
                s  += __shfl_xor_sync(0xffffffffu, s, off);
                dd += __shfl_xor_sync(0xffffffffu, dd, off);
            }
            if ((cg % LPH) == 0) {
                int h = cg / LPH;
                g_asrc[row * HEADS_T + h] = s;
                g_adst[row * HEADS_T + h] = dd;
            }
        }
    }
}

// ---------------- fused edge softmax + aggregation (gather, no atomics) ----------------
__global__ void k_gather1(const float* __restrict__ bias, int col_off) {
    int d = (blockIdx.x * blockDim.x + threadIdx.x) >> 5;
    if (d >= Nn) return;
    int lane = threadIdx.x & 31;
    int h = lane >> 3;
    float ad = g_adst[d * 4 + h];
    int beg = g_rowstart[d], end = g_rowstart[d + 1];
    float4 acc = make_float4(0.f, 0.f, 0.f, 0.f);
    float dsum = 0.f;
    int j = beg;
    for (; j + 2 <= end; j += 2) {
        int s0 = g_csr[j], s1 = g_csr[j + 1];
        float a0 = g_asrc[s0 * 4 + h] + ad;
        float a1 = g_asrc[s1 * 4 + h] + ad;
        float4 x0 = g_xp[s0 * 32 + lane];
        float4 x1 = g_xp[s1 * 32 + lane];
        a0 = (a0 > 0.f) ? a0 : 0.2f * a0;
        a1 = (a1 > 0.f) ? a1 : 0.2f * a1;
        float w0 = __expf(a0), w1 = __expf(a1);
        acc.x = fmaf(w0, x0.x, acc.x); acc.y = fmaf(w0, x0.y, acc.y);
        acc.z = fmaf(w0, x0.z, acc.z); acc.w = fmaf(w0, x0.w, acc.w);
        acc.x = fmaf(w1, x1.x, acc.x); acc.y = fmaf(w1, x1.y, acc.y);
        acc.z = fmaf(w1, x1.z, acc.z); acc.w = fmaf(w1, x1.w, acc.w);
        dsum += w0 + w1;
    }
    if (j < end) {
        int s = g_csr[j];
        float a = g_asrc[s * 4 + h] + ad;
        a = (a > 0.f) ? a : 0.2f * a;
        float wgt = __expf(a);
        float4 xv = g_xp[s * 32 + lane];
        acc.x = fmaf(wgt, xv.x, acc.x); acc.y = fmaf(wgt, xv.y, acc.y);
        acc.z = fmaf(wgt, xv.z, acc.z); acc.w = fmaf(wgt, xv.w, acc.w);
        dsum += wgt;
    }
    float inv = 1.0f / dsum;
    float4 b = ((const float4*)bias)[lane];
    float4 o;
    o.x = fmaxf(fmaf(acc.x, inv, b.x), 0.f);
    o.y = fmaxf(fmaf(acc.y, inv, b.y), 0.f);
    o.z = fmaxf(fmaf(acc.z, inv, b.z), 0.f);
    o.w = fmaxf(fmaf(acc.w, inv, b.w), 0.f);
    float* hrow = (float*)g_h + (size_t)d * 256 + col_off;
    ((float4*)hrow)[lane] = o;
}

__global__ void k_gather2(const float* __restrict__ bias, float* __restrict__ out) {
    int d = (blockIdx.x * blockDim.x + threadIdx.x) >> 5;
    if (d >= Nn) return;
    int lane = threadIdx.x & 31;
    float ad = g_adst[d];
    int beg = g_rowstart[d], end = g_rowstart[d + 1];
    float2 acc = make_float2(0.f, 0.f);
    float dsum = 0.f;
    int j = beg;
    for (; j + 2 <= end; j += 2) {
        int s0 = g_csr[j], s1 = g_csr[j + 1];
        float a0 = g_asrc[s0] + ad;
        float a1 = g_asrc[s1] + ad;
        float2 x0 = ((const float2*)g_xp)[s0 * 32 + lane];
        float2 x1 = ((const float2*)g_xp)[s1 * 32 + lane];
        a0 = (a0 > 0.f) ? a0 : 0.2f * a0;
        a1 = (a1 > 0.f) ? a1 : 0.2f * a1;
        float w0 = __expf(a0), w1 = __expf(a1);
        acc.x = fmaf(w0, x0.x, acc.x); acc.y = fmaf(w0, x0.y, acc.y);
        acc.x = fmaf(w1, x1.x, acc.x); acc.y = fmaf(w1, x1.y, acc.y);
        dsum += w0 + w1;
    }
    if (j < end) {
        int s = g_csr[j];
        float a = g_asrc[s] + ad;
        a = (a > 0.f) ? a : 0.2f * a;
        float wgt = __expf(a);
        float2 xv = ((const float2*)g_xp)[s * 32 + lane];
        acc.x = fmaf(wgt, xv.x, acc.x); acc.y = fmaf(wgt, xv.y, acc.y);
        dsum += wgt;
    }
    float inv = 1.0f / dsum;
    float2 b = ((const float2*)bias)[lane];
    float2 o;
    o.x = fmaf(acc.x, inv, b.x);
    o.y = fmaf(acc.y, inv, b.y);
    ((float2*)out)[d * 32 + lane] = o;
}

// ---------------- launch ----------------
extern "C" void kernel_launch(void* const* d_in, const int* in_sizes, int n_in,
                              void* d_out, int out_size) {
    const float* x_ppi = (const float*)d_in[0];
    const float* x_go  = (const float*)d_in[1];
    const int*   ei    = (const int*)d_in[2];
    const float* W1    = (const float*)d_in[3];
    const float* as1   = (const float*)d_in[4];
    const float* ad1   = (const float*)d_in[5];
    const float* b1    = (const float*)d_in[6];
    const float* W2    = (const float*)d_in[7];
    const float* as2   = (const float*)d_in[8];
    const float* ad2   = (const float*)d_in[9];
    const float* b2    = (const float*)d_in[10];
    float* out = (float*)d_out;

    // GEMM1: K=128, NCOL=128, RPT=2 -> smem 64KB(W) + 16KB(X) = 80KB
    // GEMM2: K=256, NCOL=64,  RPT=1 -> smem 64KB(W) + 32KB(X) = 96KB
    cudaFuncSetAttribute((const void*)k_gemm<128, 128, 2, 4, false>,
                         cudaFuncAttributeMaxDynamicSharedMemorySize, 81920);
    cudaFuncSetAttribute((const void*)k_gemm<256, 64, 1, 1, true>,
                         cudaFuncAttributeMaxDynamicSharedMemorySize, 98304);

    const int NTILES = Nn / 32;              // 3125
    const int GEMM_GRID = 296;               // 2 blocks/SM (smem-limited)
    const int NODE_BLOCKS = Nn * 32 / 256;   // warp per node
    const int EDGE_BLOCKS = (ET + 255) / 256;

    // CSR build (shared by all three convs)
    k_zero_counts<<<(Nn + 255) / 256, 256>>>();
    k_degree<<<EDGE_BLOCKS, 256>>>(ei);
    k_blockscan<<<NB, 1024>>>();
    k_scansums<<<1, 128>>>();
    k_addoff<<<NB, 1024>>>();
    k_fill<<<EDGE_BLOCKS, 256>>>(ei);

    // conv1 on x_ppi -> h[:, 0:128]
    k_gemm<128, 128, 2, 4, false><<<GEMM_GRID, 256, 81920>>>(x_ppi, W1, as1, ad1, NTILES);
    k_gather1<<<NODE_BLOCKS, 256>>>(b1, 0);

    // conv1 on x_go -> h[:, 128:256]
    k_gemm<128, 128, 2, 4, false><<<GEMM_GRID, 256, 81920>>>(x_go, W1, as1, ad1, NTILES);
    k_gather1<<<NODE_BLOCKS, 256>>>(b1, 128);

    // conv2 on h -> out
    k_gemm<256, 64, 1, 1, true><<<GEMM_GRID, 256, 98304>>>(nullptr, W2, as2, ad2, NTILES);
    k_gather2<<<NODE_BLOCKS, 256>>>(b2, out);
}

// round 5
// speedup vs baseline: 1.9087x; 1.9087x over previous
#include <cuda_runtime.h>
#include <math.h>

// Problem constants (fixed shapes)
#define Nn   100000
#define Ecnt 1600000
#define ET   (Ecnt + Nn)      // 1,700,000
#define NB   98               // ceil(Nn/1024)

// ---------------- scratch (device globals) ----------------
__device__ float4 g_xp[Nn * 32];      // xp [N,128] conv1 / xp2 [N,64] conv2
__device__ float4 g_h[Nn * 64];       // h = relu(concat) [N,256]
__device__ float  g_asrc[Nn * 4];
__device__ float  g_adst[Nn * 4];
__device__ int    g_deg[Nn];
__device__ int    g_cursor[Nn];
__device__ int    g_rowstart[Nn + 1];
__device__ int    g_csr[ET];
__device__ int    g_bsum[128];
__device__ int    g_boff[128];

// ---------------- CSR build ----------------
__global__ void k_zero_counts() {
    int i = blockIdx.x * blockDim.x + threadIdx.x;
    if (i < Nn) { g_deg[i] = 0; g_cursor[i] = 0; }
}

__global__ void k_degree(const int* __restrict__ ei) {
    int e = blockIdx.x * blockDim.x + threadIdx.x;
    if (e >= ET) return;
    int d = (e < Ecnt) ? ei[Ecnt + e] : (e - Ecnt);
    atomicAdd(&g_deg[d], 1);
}

__global__ void k_blockscan() {
    __shared__ int sh[1024];
    int b = blockIdx.x, t = threadIdx.x;
    int i = b * 1024 + t;
    int v = (i < Nn) ? g_deg[i] : 0;
    sh[t] = v;
    __syncthreads();
    for (int off = 1; off < 1024; off <<= 1) {
        int tv = (t >= off) ? sh[t - off] : 0;
        __syncthreads();
        sh[t] += tv;
        __syncthreads();
    }
    if (i < Nn) g_rowstart[i] = sh[t] - v;
    if (t == 1023) g_bsum[b] = sh[1023];
}

__global__ void k_scansums() {
    __shared__ int sh[128];
    int t = threadIdx.x;
    int v = (t < NB) ? g_bsum[t] : 0;
    sh[t] = v;
    __syncthreads();
    for (int off = 1; off < 128; off <<= 1) {
        int tv = (t >= off) ? sh[t - off] : 0;
        __syncthreads();
        sh[t] += tv;
        __syncthreads();
    }
    g_boff[t] = sh[t] - v;
    if (t == 127) g_rowstart[Nn] = sh[127];
}

__global__ void k_addoff() {
    int b = blockIdx.x, t = threadIdx.x;
    int i = b * 1024 + t;
    if (i < Nn) g_rowstart[i] += g_boff[b];
}

__global__ void k_fill(const int* __restrict__ ei) {
    int e = blockIdx.x * blockDim.x + threadIdx.x;
    if (e >= ET) return;
    int s, d;
    if (e < Ecnt) { s = ei[e]; d = ei[Ecnt + e]; }
    else          { s = d = e - Ecnt; }
    int pos = atomicAdd(&g_cursor[d], 1);
    g_csr[g_rowstart[d] + pos] = s;
}

// ---------------- GEMM: XP = X @ W  (scalar FFMA core, fused att-dot epilogue) ----
// 128 threads/block; W fully resident in smem; 32-row x tiles.
// cg = col group (float4 of output cols), rg = warp id -> rows.
// One warp covers a full row -> att dots reduced with shfl over LPH lanes.
template <int K, int NCOL, int RPT, int HEADS_T, bool IN_H>
__global__ void k_gemm(const float* __restrict__ Xext, const float* __restrict__ W,
                       const float* __restrict__ att_src, const float* __restrict__ att_dst,
                       int ntiles) {
    constexpr int CG = NCOL / 4;          // lanes covering one row
    constexpr int RG = 128 / CG;
    constexpr int ROWS = RG * RPT;        // 32
    constexpr int LPH = CG / HEADS_T;     // lanes per head
    extern __shared__ float sm[];
    float* Ws = sm;                 // K * NCOL
    float* Xs = sm + K * NCOL;      // ROWS * K
    const float* X = IN_H ? (const float*)g_h : Xext;
    float* XP = (float*)g_xp;

    int t = threadIdx.x;
    for (int i = t; i < K * NCOL / 4; i += 128)
        ((float4*)Ws)[i] = ((const float4*)W)[i];

    int cg = t % CG;
    int rg = t / CG;

    // per-thread att slices (4 cols)
    float as0 = att_src[cg * 4 + 0], as1 = att_src[cg * 4 + 1];
    float as2 = att_src[cg * 4 + 2], as3 = att_src[cg * 4 + 3];
    float ad0 = att_dst[cg * 4 + 0], ad1 = att_dst[cg * 4 + 1];
    float ad2 = att_dst[cg * 4 + 2], ad3 = att_dst[cg * 4 + 3];

    for (int tile = blockIdx.x; tile < ntiles; tile += gridDim.x) {
        __syncthreads();   // protects Ws first pass, Xs on later passes
        const float4* Xg = (const float4*)(X + (size_t)tile * ROWS * K);
        for (int i = t; i < ROWS * K / 4; i += 128)
            ((float4*)Xs)[i] = Xg[i];
        __syncthreads();

        float4 acc[RPT];
#pragma unroll
        for (int j = 0; j < RPT; j++) acc[j] = make_float4(0.f, 0.f, 0.f, 0.f);

        for (int k4 = 0; k4 < K / 4; k4++) {
            float xb[RPT][4];
#pragma unroll
            for (int j = 0; j < RPT; j++) {
                float4 tmp = *(const float4*)&Xs[(rg * RPT + j) * K + k4 * 4];
                xb[j][0] = tmp.x; xb[j][1] = tmp.y; xb[j][2] = tmp.z; xb[j][3] = tmp.w;
            }
#pragma unroll
            for (int kk = 0; kk < 4; kk++) {
                float4 wv = ((const float4*)Ws)[(k4 * 4 + kk) * CG + cg];
#pragma unroll
                for (int j = 0; j < RPT; j++) {
                    acc[j].x = fmaf(wv.x, xb[j][kk], acc[j].x);
                    acc[j].y = fmaf(wv.y, xb[j][kk], acc[j].y);
                    acc[j].z = fmaf(wv.z, xb[j][kk], acc[j].z);
                    acc[j].w = fmaf(wv.w, xb[j][kk], acc[j].w);
                }
            }
        }

        float4* Og = (float4*)(XP + (size_t)tile * ROWS * NCOL);
#pragma unroll
        for (int j = 0; j < RPT; j++) {
            Og[(rg * RPT + j) * CG + cg] = acc[j];
            // fused attention dots for this row
            float s = acc[j].x * as0 + acc[j].y * as1 + acc[j].z * as2 + acc[j].w * as3;
            float dd = acc[j].x * ad0 + acc[j].y * ad1 + acc[j].z * ad2 + acc[j].w * ad3;
#pragma unroll
            for (int off = LPH / 2; off; off >>= 1) {
                s  += __shfl_xor_sync(0xffffffffu, s, off);
                dd += __shfl_xor_sync(0xffffffffu, dd, off);
            }
            if ((cg % LPH) == 0) {
                int row = tile * ROWS + rg * RPT + j;
                int h = cg / LPH;
                g_asrc[row * HEADS_T + h] = s;
                g_adst[row * HEADS_T + h] = dd;
            }
        }
    }
}

// ---------------- fused edge softmax + aggregation (gather, no atomics) ----------------
__global__ void k_gather1(const float* __restrict__ bias, int col_off) {
    int d = (blockIdx.x * blockDim.x + threadIdx.x) >> 5;
    if (d >= Nn) return;
    int lane = threadIdx.x & 31;
    int h = lane >> 3;
    float ad = g_adst[d * 4 + h];
    int beg = g_rowstart[d], end = g_rowstart[d + 1];
    float4 acc = make_float4(0.f, 0.f, 0.f, 0.f);
    float dsum = 0.f;
    int j = beg;
    for (; j + 2 <= end; j += 2) {
        int s0 = g_csr[j], s1 = g_csr[j + 1];
        float a0 = g_asrc[s0 * 4 + h] + ad;
        float a1 = g_asrc[s1 * 4 + h] + ad;
        float4 x0 = g_xp[s0 * 32 + lane];
        float4 x1 = g_xp[s1 * 32 + lane];
        a0 = (a0 > 0.f) ? a0 : 0.2f * a0;
        a1 = (a1 > 0.f) ? a1 : 0.2f * a1;
        float w0 = __expf(a0), w1 = __expf(a1);
        acc.x = fmaf(w0, x0.x, acc.x); acc.y = fmaf(w0, x0.y, acc.y);
        acc.z = fmaf(w0, x0.z, acc.z); acc.w = fmaf(w0, x0.w, acc.w);
        acc.x = fmaf(w1, x1.x, acc.x); acc.y = fmaf(w1, x1.y, acc.y);
        acc.z = fmaf(w1, x1.z, acc.z); acc.w = fmaf(w1, x1.w, acc.w);
        dsum += w0 + w1;
    }
    if (j < end) {
        int s = g_csr[j];
        float a = g_asrc[s * 4 + h] + ad;
        a = (a > 0.f) ? a : 0.2f * a;
        float wgt = __expf(a);
        float4 xv = g_xp[s * 32 + lane];
        acc.x = fmaf(wgt, xv.x, acc.x); acc.y = fmaf(wgt, xv.y, acc.y);
        acc.z = fmaf(wgt, xv.z, acc.z); acc.w = fmaf(wgt, xv.w, acc.w);
        dsum += wgt;
    }
    float inv = 1.0f / dsum;
    float4 b = ((const float4*)bias)[lane];
    float4 o;
    o.x = fmaxf(fmaf(acc.x, inv, b.x), 0.f);
    o.y = fmaxf(fmaf(acc.y, inv, b.y), 0.f);
    o.z = fmaxf(fmaf(acc.z, inv, b.z), 0.f);
    o.w = fmaxf(fmaf(acc.w, inv, b.w), 0.f);
    float* hrow = (float*)g_h + (size_t)d * 256 + col_off;
    ((float4*)hrow)[lane] = o;
}

__global__ void k_gather2(const float* __restrict__ bias, float* __restrict__ out) {
    int d = (blockIdx.x * blockDim.x + threadIdx.x) >> 5;
    if (d >= Nn) return;
    int lane = threadIdx.x & 31;
    float ad = g_adst[d];
    int beg = g_rowstart[d], end = g_rowstart[d + 1];
    float2 acc = make_float2(0.f, 0.f);
    float dsum = 0.f;
    int j = beg;
    for (; j + 2 <= end; j += 2) {
        int s0 = g_csr[j], s1 = g_csr[j + 1];
        float a0 = g_asrc[s0] + ad;
        float a1 = g_asrc[s1] + ad;
        float2 x0 = ((const float2*)g_xp)[s0 * 32 + lane];
        float2 x1 = ((const float2*)g_xp)[s1 * 32 + lane];
        a0 = (a0 > 0.f) ? a0 : 0.2f * a0;
        a1 = (a1 > 0.f) ? a1 : 0.2f * a1;
        float w0 = __expf(a0), w1 = __expf(a1);
        acc.x = fmaf(w0, x0.x, acc.x); acc.y = fmaf(w0, x0.y, acc.y);
        acc.x = fmaf(w1, x1.x, acc.x); acc.y = fmaf(w1, x1.y, acc.y);
        dsum += w0 + w1;
    }
    if (j < end) {
        int s = g_csr[j];
        float a = g_asrc[s] + ad;
        a = (a > 0.f) ? a : 0.2f * a;
        float wgt = __expf(a);
        float2 xv = ((const float2*)g_xp)[s * 32 + lane];
        acc.x = fmaf(wgt, xv.x, acc.x); acc.y = fmaf(wgt, xv.y, acc.y);
        dsum += wgt;
    }
    float inv = 1.0f / dsum;
    float2 b = ((const float2*)bias)[lane];
    float2 o;
    o.x = fmaf(acc.x, inv, b.x);
    o.y = fmaf(acc.y, inv, b.y);
    ((float2*)out)[d * 32 + lane] = o;
}

// ---------------- launch ----------------
extern "C" void kernel_launch(void* const* d_in, const int* in_sizes, int n_in,
                              void* d_out, int out_size) {
    const float* x_ppi = (const float*)d_in[0];
    const float* x_go  = (const float*)d_in[1];
    const int*   ei    = (const int*)d_in[2];
    const float* W1    = (const float*)d_in[3];
    const float* as1   = (const float*)d_in[4];
    const float* ad1   = (const float*)d_in[5];
    const float* b1    = (const float*)d_in[6];
    const float* W2    = (const float*)d_in[7];
    const float* as2   = (const float*)d_in[8];
    const float* ad2   = (const float*)d_in[9];
    const float* b2    = (const float*)d_in[10];
    float* out = (float*)d_out;

    // GEMM1: K=128, NCOL=128, RPT=8 -> smem 64KB(W) + 16KB(X) = 80KB
    // GEMM2: K=256, NCOL=64,  RPT=4 -> smem 64KB(W) + 32KB(X) = 96KB
    cudaFuncSetAttribute((const void*)k_gemm<128, 128, 8, 4, false>,
                         cudaFuncAttributeMaxDynamicSharedMemorySize, 81920);
    cudaFuncSetAttribute((const void*)k_gemm<256, 64, 4, 1, true>,
                         cudaFuncAttributeMaxDynamicSharedMemorySize, 98304);

    const int NTILES = Nn / 32;              // 3125
    const int GEMM_GRID = 1184;              // grid-stride over tiles
    const int NODE_BLOCKS = Nn * 32 / 256;   // warp per node
    const int EDGE_BLOCKS = (ET + 255) / 256;

    // CSR build (shared by all three convs)
    k_zero_counts<<<(Nn + 255) / 256, 256>>>();
    k_degree<<<EDGE_BLOCKS, 256>>>(ei);
    k_blockscan<<<NB, 1024>>>();
    k_scansums<<<1, 128>>>();
    k_addoff<<<NB, 1024>>>();
    k_fill<<<EDGE_BLOCKS, 256>>>(ei);

    // conv1 on x_ppi -> h[:, 0:128]
    k_gemm<128, 128, 8, 4, false><<<GEMM_GRID, 128, 81920>>>(x_ppi, W1, as1, ad1, NTILES);
    k_gather1<<<NODE_BLOCKS, 256>>>(b1, 0);

    // conv1 on x_go -> h[:, 128:256]
    k_gemm<128, 128, 8, 4, false><<<GEMM_GRID, 128, 81920>>>(x_go, W1, as1, ad1, NTILES);
    k_gather1<<<NODE_BLOCKS, 256>>>(b1, 128);

    // conv2 on h -> out
    k_gemm<256, 64, 4, 1, true><<<GEMM_GRID, 128, 98304>>>(nullptr, W2, as2, ad2, NTILES);
    k_gather2<<<NODE_BLOCKS, 256>>>(b2, out);
}